// round 6
// baseline (speedup 1.0000x reference)
#include <cuda_runtime.h>
#include <cuda_bf16.h>
#include <math.h>
#include <cstdint>

// Problem dims
constexpr int Bb = 4;
constexpr int Ss = 2048;
constexpr int Dd = 1024;
constexpr int Hh = 16;
constexpr int HD = 64;
constexpr int Mrows = Bb * Ss;          // 8192

// ---------------------------------------------------------------------------
// Device-global scratch. All bf16 hi/lo split pairs.
// ---------------------------------------------------------------------------
__device__ __nv_bfloat16 g_xh[(size_t)Mrows * Dd];
__device__ __nv_bfloat16 g_xl[(size_t)Mrows * Dd];
__device__ __nv_bfloat16 g_wah[(size_t)3 * Dd * Dd];   // W_attn^T [3072,1024]
__device__ __nv_bfloat16 g_wal[(size_t)3 * Dd * Dd];
__device__ __nv_bfloat16 g_wph[(size_t)Dd * Dd];       // W_proj^T [1024,1024]
__device__ __nv_bfloat16 g_wpl[(size_t)Dd * Dd];
// q/k/v in [b*H+h][s][hd] layout (q pre-scaled by 1/8)
__device__ __nv_bfloat16 g_qh[(size_t)Bb * Hh * Ss * HD];
__device__ __nv_bfloat16 g_ql[(size_t)Bb * Hh * Ss * HD];
__device__ __nv_bfloat16 g_kh[(size_t)Bb * Hh * Ss * HD];
__device__ __nv_bfloat16 g_kl[(size_t)Bb * Hh * Ss * HD];
__device__ __nv_bfloat16 g_vh[(size_t)Bb * Hh * Ss * HD];
__device__ __nv_bfloat16 g_vl[(size_t)Bb * Hh * Ss * HD];
// attention output [b][s][d]
__device__ __nv_bfloat16 g_yh[(size_t)Mrows * Dd];
__device__ __nv_bfloat16 g_yl[(size_t)Mrows * Dd];

// ---------------------------------------------------------------------------
// Helpers
// ---------------------------------------------------------------------------
__device__ __forceinline__ uint32_t smem_u32(const void* p) {
    uint32_t a;
    asm("{ .reg .u64 t; cvta.to.shared.u64 t, %1; cvt.u32.u64 %0, t; }"
        : "=r"(a) : "l"(p));
    return a;
}

__device__ __forceinline__ void ldsm_x4(uint32_t (&r)[4], uint32_t addr) {
    asm volatile("ldmatrix.sync.aligned.m8n8.x4.shared.b16 {%0,%1,%2,%3}, [%4];"
        : "=r"(r[0]), "=r"(r[1]), "=r"(r[2]), "=r"(r[3]) : "r"(addr));
}
__device__ __forceinline__ void ldsm_x4t(uint32_t (&r)[4], uint32_t addr) {
    asm volatile("ldmatrix.sync.aligned.m8n8.x4.trans.shared.b16 {%0,%1,%2,%3}, [%4];"
        : "=r"(r[0]), "=r"(r[1]), "=r"(r[2]), "=r"(r[3]) : "r"(addr));
}
__device__ __forceinline__ void mma16816(float (&c)[4], const uint32_t (&a)[4],
                                         uint32_t b0, uint32_t b1) {
    asm volatile(
        "mma.sync.aligned.m16n8k16.row.col.f32.bf16.bf16.f32 "
        "{%0,%1,%2,%3}, {%4,%5,%6,%7}, {%8,%9}, {%0,%1,%2,%3};"
        : "+f"(c[0]), "+f"(c[1]), "+f"(c[2]), "+f"(c[3])
        : "r"(a[0]), "r"(a[1]), "r"(a[2]), "r"(a[3]), "r"(b0), "r"(b1));
}

#define CP16(dst, src) \
    asm volatile("cp.async.cg.shared.global [%0], [%1], 16;" :: "r"(dst), "l"(src))
#define CP_COMMIT() asm volatile("cp.async.commit_group;" ::: "memory")

__device__ __forceinline__ void split2(float v0, float v1, uint32_t& hi, uint32_t& lo) {
    __nv_bfloat16 h0 = __float2bfloat16(v0), h1 = __float2bfloat16(v1);
    float r0 = v0 - __bfloat162float(h0);
    float r1 = v1 - __bfloat162float(h1);
    __nv_bfloat162 H(h0, h1);
    __nv_bfloat162 L(__float2bfloat16(r0), __float2bfloat16(r1));
    hi = *(uint32_t*)&H;
    lo = *(uint32_t*)&L;
}

// ---------------------------------------------------------------------------
// fp32 -> bf16 hi/lo split for x
// ---------------------------------------------------------------------------
__global__ __launch_bounds__(256) void split_x_kernel(const float* __restrict__ in, int n4)
{
    int i = blockIdx.x * blockDim.x + threadIdx.x;
    if (i >= n4) return;
    float4 v = ((const float4*)in)[i];
    uint32_t h0, l0, h1, l1;
    split2(v.x, v.y, h0, l0);
    split2(v.z, v.w, h1, l1);
    ((uint32_t*)g_xh)[i * 2 + 0] = h0;
    ((uint32_t*)g_xh)[i * 2 + 1] = h1;
    ((uint32_t*)g_xl)[i * 2 + 0] = l0;
    ((uint32_t*)g_xl)[i * 2 + 1] = l1;
}

// ---------------------------------------------------------------------------
// Transpose + split: W [K=1024, N] -> Wt hi/lo [N, K]
// ---------------------------------------------------------------------------
template <int TGT>
__global__ __launch_bounds__(256) void tsplit_kernel(const float* __restrict__ W, int Ncols)
{
    __shared__ float t[32][33];
    int n0 = blockIdx.x * 32, k0 = blockIdx.y * 32;
    int tx = threadIdx.x, ty = threadIdx.y;   // (32,8)
#pragma unroll
    for (int i = 0; i < 32; i += 8)
        t[ty + i][tx] = W[(size_t)(k0 + ty + i) * Ncols + n0 + tx];
    __syncthreads();
    __nv_bfloat16* Hi = (TGT == 0) ? g_wah : g_wph;
    __nv_bfloat16* Lo = (TGT == 0) ? g_wal : g_wpl;
#pragma unroll
    for (int i = 0; i < 32; i += 8) {
        float v = t[tx][ty + i];
        __nv_bfloat16 h = __float2bfloat16(v);
        __nv_bfloat16 l = __float2bfloat16(v - __bfloat162float(h));
        size_t o = (size_t)(n0 + ty + i) * 1024 + k0 + tx;
        Hi[o] = h;
        Lo[o] = l;
    }
}

// ---------------------------------------------------------------------------
// mma.sync GEMM: C[M=8192, NTOT] = A[M,1024] @ Wt[NTOT,1024]^T + bias
// bf16 split 3-term, term-major issue order (dependency distance 4).
// Block 128x128, 8 warps (32x64 warp tile), K-chunk 32, double buffered.
// ---------------------------------------------------------------------------
constexpr int GSTRIDE = 80;                 // bytes per smem row (40 halves)
constexpr int GTILE = 128 * GSTRIDE;        // 10240 B per array
constexpr int GSTAGE = 4 * GTILE;           // Ah Al Bh Bl = 40960
constexpr int GEMM_SMEM = 2 * GSTAGE;       // 81920

template <int NTOT, int MODE>
__global__ __launch_bounds__(256, 2) void mgemm_kernel(const float* __restrict__ bias,
                                                       float* __restrict__ Out)
{
    extern __shared__ __align__(128) uint8_t smraw[];
    const uint32_t sb = smem_u32(smraw);
    const int tid = threadIdx.x;
    const int wid = tid >> 5, lane = tid & 31;
    const int wM = wid & 3, wN = wid >> 2;
    const int lr = lane & 7, lm = lane >> 3;
    const int gq = lane >> 2, cq = lane & 3;
    const int bm = blockIdx.y * 128;
    const int bn = blockIdx.x * 128;

    const __nv_bfloat16* __restrict__ Ah = (MODE == 0) ? g_xh : g_yh;
    const __nv_bfloat16* __restrict__ Al = (MODE == 0) ? g_xl : g_yl;
    const __nv_bfloat16* __restrict__ Bh = (MODE == 0) ? g_wah : g_wph;
    const __nv_bfloat16* __restrict__ Bl = (MODE == 0) ? g_wal : g_wpl;

    float c[2][8][4];
#pragma unroll
    for (int a = 0; a < 2; a++)
#pragma unroll
        for (int b = 0; b < 8; b++)
#pragma unroll
            for (int d = 0; d < 4; d++) c[a][b][d] = 0.0f;

    auto fill = [&](int st, int kc) {
        uint32_t base = sb + st * GSTAGE;
#pragma unroll
        for (int i = tid; i < 512; i += 256) {
            int row = i >> 2, seg = i & 3;
            uint32_t off = (uint32_t)(row * GSTRIDE + seg * 16);
            size_t ga = (size_t)(bm + row) * 1024 + kc * 32 + seg * 8;
            size_t gb = (size_t)(bn + row) * 1024 + kc * 32 + seg * 8;
            CP16(base + off,             Ah + ga);
            CP16(base + GTILE + off,     Al + ga);
            CP16(base + 2 * GTILE + off, Bh + gb);
            CP16(base + 3 * GTILE + off, Bl + gb);
        }
        CP_COMMIT();
    };

    fill(0, 0);
    fill(1, 1);

    for (int kc = 0; kc < 32; kc++) {
        const int st = kc & 1;
        if (kc == 31) asm volatile("cp.async.wait_group 0;" ::: "memory");
        else          asm volatile("cp.async.wait_group 1;" ::: "memory");
        __syncthreads();

        const uint32_t base = sb + st * GSTAGE;
#pragma unroll
        for (int ks = 0; ks < 2; ks++) {
            uint32_t ah[2][4], al[2][4];
#pragma unroll
            for (int mf = 0; mf < 2; mf++) {
                int row = wM * 32 + mf * 16 + (lm & 1) * 8 + lr;
                int col = ks * 16 + (lm >> 1) * 8;
                uint32_t ad = base + row * GSTRIDE + col * 2;
                ldsm_x4(ah[mf], ad);
                ldsm_x4(al[mf], ad + GTILE);
            }
#pragma unroll
            for (int jj = 0; jj < 4; jj++) {
                int rowB = wN * 64 + jj * 16 + (lm >> 1) * 8 + lr;
                int colB = ks * 16 + (lm & 1) * 8;
                uint32_t adB = base + 2 * GTILE + rowB * GSTRIDE + colB * 2;
                uint32_t bh_[4], bl_[4];
                ldsm_x4(bh_, adB);
                ldsm_x4(bl_, adB + GTILE);
                // term-major: 4 independent MMAs between accumulator reuses
#pragma unroll
                for (int mf = 0; mf < 2; mf++)
#pragma unroll
                    for (int nn = 0; nn < 2; nn++)
                        mma16816(c[mf][jj * 2 + nn], ah[mf], bh_[nn * 2], bh_[nn * 2 + 1]);
#pragma unroll
                for (int mf = 0; mf < 2; mf++)
#pragma unroll
                    for (int nn = 0; nn < 2; nn++)
                        mma16816(c[mf][jj * 2 + nn], ah[mf], bl_[nn * 2], bl_[nn * 2 + 1]);
#pragma unroll
                for (int mf = 0; mf < 2; mf++)
#pragma unroll
                    for (int nn = 0; nn < 2; nn++)
                        mma16816(c[mf][jj * 2 + nn], al[mf], bh_[nn * 2], bh_[nn * 2 + 1]);
            }
        }
        __syncthreads();
        if (kc + 2 < 32) fill(st, kc + 2);
    }

    // Epilogue
#pragma unroll
    for (int mf = 0; mf < 2; mf++) {
        int row0 = bm + wM * 32 + mf * 16 + gq;
#pragma unroll
        for (int j = 0; j < 8; j++) {
            int n = bn + wN * 64 + j * 8 + 2 * cq;
            if (MODE == 0) {
                float b0 = bias[n], b1 = bias[n + 1];
                const int which = n >> 10;
                const int dd = n & 1023;
                const int h = dd >> 6, hd = dd & 63;
                __nv_bfloat16* ph = (which == 0) ? g_qh : (which == 1) ? g_kh : g_vh;
                __nv_bfloat16* pl = (which == 0) ? g_ql : (which == 1) ? g_kl : g_vl;
                const float sc = (which == 0) ? 0.125f : 1.0f;
#pragma unroll
                for (int half = 0; half < 2; half++) {
                    int m = row0 + half * 8;
                    int b_ = m >> 11, s_ = m & 2047;
                    float v0 = (c[mf][j][half * 2 + 0] + b0) * sc;
                    float v1 = (c[mf][j][half * 2 + 1] + b1) * sc;
                    uint32_t hiw, low;
                    split2(v0, v1, hiw, low);
                    size_t idx = (((size_t)(b_ * Hh + h)) * Ss + s_) * HD + hd;
                    *(uint32_t*)&ph[idx] = hiw;
                    *(uint32_t*)&pl[idx] = low;
                }
            } else {
                float b0 = bias[n], b1 = bias[n + 1];
#pragma unroll
                for (int half = 0; half < 2; half++) {
                    int m = row0 + half * 8;
                    float2 o;
                    o.x = c[mf][j][half * 2 + 0] + b0;
                    o.y = c[mf][j][half * 2 + 1] + b1;
                    *(float2*)&Out[(size_t)m * NTOT + n] = o;
                }
            }
        }
    }
}

// ---------------------------------------------------------------------------
// Flash attention: 256 thr = 8 warps, Q tile 128 rows, K/V tile 64.
// cp.async double-buffered K/V stages + dedicated Q smem region.
// ---------------------------------------------------------------------------
constexpr int ATB = 64 * 144;                 // 9216 B per K/V array
constexpr int ATT_STAGE = 4 * ATB;            // Kh Kl Vh Vl = 36864
constexpr int ATT_QOFF = 2 * ATT_STAGE;       // Q region: Qh[128][144] + Ql
constexpr int ATT_QHL = 128 * 144;            // 18432
constexpr int ATT_SMEM = ATT_QOFF + 2 * ATT_QHL;   // 110592

__global__ __launch_bounds__(256, 2) void attn_kernel()
{
    extern __shared__ __align__(128) uint8_t smd[];
    const uint32_t sb = smem_u32(smd);
    const int qt = blockIdx.x, bh = blockIdx.y;
    const int tid = threadIdx.x;
    const int w = tid >> 5, lane = tid & 31;
    const int lr = lane & 7, lm = lane >> 3;
    const int gq = lane >> 2, cq = lane & 3;

    const size_t bhoff = (size_t)bh * Ss * HD;
    const uint32_t qb = sb + ATT_QOFF;

    // stage Q tile (128 rows)
    {
        const uint4* qh4 = (const uint4*)(g_qh + bhoff + (size_t)qt * 128 * HD);
        const uint4* ql4 = (const uint4*)(g_ql + bhoff + (size_t)qt * 128 * HD);
#pragma unroll
        for (int i = tid; i < 1024; i += 256) {
            int row = i >> 3, seg = i & 7;
            uint32_t o = (uint32_t)(row * 144 + seg * 16);
            *(uint4*)(smd + ATT_QOFF + o) = qh4[row * 8 + seg];
            *(uint4*)(smd + ATT_QOFF + ATT_QHL + o) = ql4[row * 8 + seg];
        }
    }

    const int NT = 2 * qt + 2;    // number of 64-key tiles

    auto fill = [&](int st, int kt) {
        uint32_t base = sb + st * ATT_STAGE;
        const size_t ko = bhoff + (size_t)kt * 64 * HD;
#pragma unroll
        for (int t = 0; t < 2; t++) {
            int idx = tid + t * 256;          // 0..511
            int row = idx >> 3, seg = idx & 7;
            uint32_t o = (uint32_t)(row * 144 + seg * 16);
            size_t go = ko + (size_t)row * HD + seg * 8;
            CP16(base + o,           g_kh + go);
            CP16(base + ATB + o,     g_kl + go);
            CP16(base + 2 * ATB + o, g_vh + go);
            CP16(base + 3 * ATB + o, g_vl + go);
        }
        CP_COMMIT();
    };

    fill(0, 0);
    fill(1, 1);

    float m0 = -1e30f, m1 = -1e30f, l0 = 0.0f, l1 = 0.0f;
    float acc[8][4];
#pragma unroll
    for (int j = 0; j < 8; j++)
#pragma unroll
        for (int d = 0; d < 4; d++) acc[j][d] = 0.0f;

    for (int kt = 0; kt < NT; kt++) {
        const int st = kt & 1;
        if (kt + 1 < NT) asm volatile("cp.async.wait_group 1;" ::: "memory");
        else             asm volatile("cp.async.wait_group 0;" ::: "memory");
        __syncthreads();

        const uint32_t base = sb + st * ATT_STAGE;

        // S = Q @ K^T (3-term split, term-major)
        float s[8][4];
#pragma unroll
        for (int j = 0; j < 8; j++)
#pragma unroll
            for (int d = 0; d < 4; d++) s[j][d] = 0.0f;

#pragma unroll
        for (int ks = 0; ks < 4; ks++) {
            uint32_t qh_[4], ql_[4];
            {
                int rowQ = w * 16 + (lm & 1) * 8 + lr;
                int colQ = ks * 16 + (lm >> 1) * 8;
                uint32_t adQ = qb + rowQ * 144 + colQ * 2;
                ldsm_x4(qh_, adQ);
                ldsm_x4(ql_, adQ + ATT_QHL);
            }
#pragma unroll
            for (int jj = 0; jj < 2; jj++) {
                // load two adjacent 16-col B blocks (4 independent n-frags)
                uint32_t bh0[4], bl0[4], bh1[4], bl1[4];
                {
                    int rowB = jj * 32 + (lm >> 1) * 8 + lr;
                    int colB = ks * 16 + (lm & 1) * 8;
                    uint32_t adB = base + rowB * 144 + colB * 2;
                    ldsm_x4(bh0, adB);
                    ldsm_x4(bl0, adB + ATB);
                    ldsm_x4(bh1, adB + 16 * 144);
                    ldsm_x4(bl1, adB + 16 * 144 + ATB);
                }
                int j0 = jj * 4;
                // term-major: 4 independent per term
                mma16816(s[j0 + 0], qh_, bh0[0], bh0[1]);
                mma16816(s[j0 + 1], qh_, bh0[2], bh0[3]);
                mma16816(s[j0 + 2], qh_, bh1[0], bh1[1]);
                mma16816(s[j0 + 3], qh_, bh1[2], bh1[3]);
                mma16816(s[j0 + 0], qh_, bl0[0], bl0[1]);
                mma16816(s[j0 + 1], qh_, bl0[2], bl0[3]);
                mma16816(s[j0 + 2], qh_, bl1[0], bl1[1]);
                mma16816(s[j0 + 3], qh_, bl1[2], bl1[3]);
                mma16816(s[j0 + 0], ql_, bh0[0], bh0[1]);
                mma16816(s[j0 + 1], ql_, bh0[2], bh0[3]);
                mma16816(s[j0 + 2], ql_, bh1[0], bh1[1]);
                mma16816(s[j0 + 3], ql_, bh1[2], bh1[3]);
            }
        }

        // causal mask (tiles crossing this warp's rows)
        if (kt * 64 + 63 > qt * 128 + w * 16) {
            int rg0 = qt * 128 + w * 16 + gq, rg1 = rg0 + 8;
#pragma unroll
            for (int j = 0; j < 8; j++) {
                int ck = kt * 64 + j * 8 + 2 * cq;
                if (ck > rg0)     s[j][0] = -1e30f;
                if (ck + 1 > rg0) s[j][1] = -1e30f;
                if (ck > rg1)     s[j][2] = -1e30f;
                if (ck + 1 > rg1) s[j][3] = -1e30f;
            }
        }

        // online softmax
        float tm0 = -1e30f, tm1 = -1e30f;
#pragma unroll
        for (int j = 0; j < 8; j++) {
            tm0 = fmaxf(tm0, fmaxf(s[j][0], s[j][1]));
            tm1 = fmaxf(tm1, fmaxf(s[j][2], s[j][3]));
        }
        tm0 = fmaxf(tm0, __shfl_xor_sync(0xffffffffu, tm0, 1));
        tm0 = fmaxf(tm0, __shfl_xor_sync(0xffffffffu, tm0, 2));
        tm1 = fmaxf(tm1, __shfl_xor_sync(0xffffffffu, tm1, 1));
        tm1 = fmaxf(tm1, __shfl_xor_sync(0xffffffffu, tm1, 2));
        float mn0 = fmaxf(m0, tm0), mn1 = fmaxf(m1, tm1);
        float a0 = __expf(m0 - mn0), a1 = __expf(m1 - mn1);
        float rs0 = 0.0f, rs1 = 0.0f;
#pragma unroll
        for (int j = 0; j < 8; j++) {
            s[j][0] = __expf(s[j][0] - mn0);
            s[j][1] = __expf(s[j][1] - mn0);
            s[j][2] = __expf(s[j][2] - mn1);
            s[j][3] = __expf(s[j][3] - mn1);
            rs0 += s[j][0] + s[j][1];
            rs1 += s[j][2] + s[j][3];
        }
        rs0 += __shfl_xor_sync(0xffffffffu, rs0, 1);
        rs0 += __shfl_xor_sync(0xffffffffu, rs0, 2);
        rs1 += __shfl_xor_sync(0xffffffffu, rs1, 1);
        rs1 += __shfl_xor_sync(0xffffffffu, rs1, 2);
        l0 = l0 * a0 + rs0;
        l1 = l1 * a1 + rs1;
        m0 = mn0;
        m1 = mn1;
#pragma unroll
        for (int j = 0; j < 8; j++) {
            acc[j][0] *= a0; acc[j][1] *= a0;
            acc[j][2] *= a1; acc[j][3] *= a1;
        }

        // O += P @ V (3-term, P repacked in registers, term-major)
#pragma unroll
        for (int ks = 0; ks < 4; ks++) {
            uint32_t pah[4], pal[4];
            split2(s[2 * ks][0],     s[2 * ks][1],     pah[0], pal[0]);
            split2(s[2 * ks][2],     s[2 * ks][3],     pah[1], pal[1]);
            split2(s[2 * ks + 1][0], s[2 * ks + 1][1], pah[2], pal[2]);
            split2(s[2 * ks + 1][2], s[2 * ks + 1][3], pah[3], pal[3]);
#pragma unroll
            for (int jj = 0; jj < 2; jj++) {
                uint32_t vh0[4], vl0[4], vh1[4], vl1[4];
                {
                    int rowV = ks * 16 + (lm & 1) * 8 + lr;
                    int colV = jj * 32 + (lm >> 1) * 8;
                    uint32_t adV = base + 2 * ATB + rowV * 144 + colV * 2;
                    ldsm_x4t(vh0, adV);
                    ldsm_x4t(vl0, adV + ATB);
                    ldsm_x4t(vh1, adV + 32);
                    ldsm_x4t(vl1, adV + 32 + ATB);
                }
                int j0 = jj * 4;
                mma16816(acc[j0 + 0], pah, vh0[0], vh0[1]);
                mma16816(acc[j0 + 1], pah, vh0[2], vh0[3]);
                mma16816(acc[j0 + 2], pah, vh1[0], vh1[1]);
                mma16816(acc[j0 + 3], pah, vh1[2], vh1[3]);
                mma16816(acc[j0 + 0], pah, vl0[0], vl0[1]);
                mma16816(acc[j0 + 1], pah, vl0[2], vl0[3]);
                mma16816(acc[j0 + 2], pah, vl1[0], vl1[1]);
                mma16816(acc[j0 + 3], pah, vl1[2], vl1[3]);
                mma16816(acc[j0 + 0], pal, vh0[0], vh0[1]);
                mma16816(acc[j0 + 1], pal, vh0[2], vh0[3]);
                mma16816(acc[j0 + 2], pal, vh1[0], vh1[1]);
                mma16816(acc[j0 + 3], pal, vh1[2], vh1[3]);
            }
        }
        __syncthreads();
        if (kt + 2 < NT) fill(st, kt + 2);
    }

    // epilogue: normalize, split, store y
    float i0 = 1.0f / l0, i1 = 1.0f / l1;
    const int b_ = bh >> 4, h = bh & 15;
    const int sr0 = qt * 128 + w * 16 + gq, sr1 = sr0 + 8;
#pragma unroll
    for (int j = 0; j < 8; j++) {
        int hd = j * 8 + 2 * cq;
        uint32_t hiw, low;
        split2(acc[j][0] * i0, acc[j][1] * i0, hiw, low);
        size_t o0 = ((size_t)b_ * Ss + sr0) * Dd + h * HD + hd;
        *(uint32_t*)&g_yh[o0] = hiw;
        *(uint32_t*)&g_yl[o0] = low;
        split2(acc[j][2] * i1, acc[j][3] * i1, hiw, low);
        size_t o1 = ((size_t)b_ * Ss + sr1) * Dd + h * HD + hd;
        *(uint32_t*)&g_yh[o1] = hiw;
        *(uint32_t*)&g_yl[o1] = low;
    }
}

// ---------------------------------------------------------------------------
extern "C" void kernel_launch(void* const* d_in, const int* in_sizes, int n_in,
                              void* d_out, int out_size)
{
    const float* x      = (const float*)d_in[0];
    const float* W_attn = (const float*)d_in[1];
    const float* b_attn = (const float*)d_in[2];
    const float* W_proj = (const float*)d_in[3];
    const float* b_proj = (const float*)d_in[4];
    float* out = (float*)d_out;

    cudaFuncSetAttribute(mgemm_kernel<3072, 0>,
                         cudaFuncAttributeMaxDynamicSharedMemorySize, GEMM_SMEM);
    cudaFuncSetAttribute(mgemm_kernel<1024, 1>,
                         cudaFuncAttributeMaxDynamicSharedMemorySize, GEMM_SMEM);
    cudaFuncSetAttribute(attn_kernel,
                         cudaFuncAttributeMaxDynamicSharedMemorySize, ATT_SMEM);

    // 0) precision splits
    int n4 = Mrows * Dd / 4;
    split_x_kernel<<<(n4 + 255) / 256, 256>>>(x, n4);
    tsplit_kernel<0><<<dim3(3072 / 32, 1024 / 32), dim3(32, 8)>>>(W_attn, 3072);
    tsplit_kernel<1><<<dim3(1024 / 32, 1024 / 32), dim3(32, 8)>>>(W_proj, 1024);

    // 1) QKV GEMM -> q/k/v bf16 hi/lo
    mgemm_kernel<3072, 0><<<dim3(3072 / 128, Mrows / 128), 256, GEMM_SMEM>>>(
        b_attn, nullptr);

    // 2) causal flash attention -> y bf16 hi/lo (128-row q tiles)
    attn_kernel<<<dim3(Ss / 128, Bb * Hh), 256, ATT_SMEM>>>();

    // 3) output projection -> out fp32
    mgemm_kernel<1024, 1><<<dim3(1024 / 128, Mrows / 128), 256, GEMM_SMEM>>>(
        b_proj, out);
}

// round 8
// speedup vs baseline: 3.8327x; 3.8327x over previous
#include <cuda_runtime.h>
#include <cuda_fp16.h>
#include <math.h>
#include <cstdint>

// Problem dims
constexpr int Bb = 4;
constexpr int Ss = 2048;
constexpr int Dd = 1024;
constexpr int Hh = 16;
constexpr int HD = 64;
constexpr int Mrows = Bb * Ss;          // 8192

// ---------------------------------------------------------------------------
// Device-global scratch (fp16 single precision-term operands)
// ---------------------------------------------------------------------------
__device__ __half g_x16[(size_t)Mrows * Dd];
__device__ __half g_wa16[(size_t)3 * Dd * Dd];   // W_attn^T [3072,1024]
__device__ __half g_wp16[(size_t)Dd * Dd];       // W_proj^T [1024,1024]
// q/k/v in [b*H+h][s][hd] layout (q pre-scaled by 1/8)
__device__ __half g_q16[(size_t)Bb * Hh * Ss * HD];
__device__ __half g_k16[(size_t)Bb * Hh * Ss * HD];
__device__ __half g_v16[(size_t)Bb * Hh * Ss * HD];
// attention output [b][s][d]
__device__ __half g_y16[(size_t)Mrows * Dd];

// ---------------------------------------------------------------------------
// Helpers
// ---------------------------------------------------------------------------
__device__ __forceinline__ uint32_t smem_u32(const void* p) {
    uint32_t a;
    asm("{ .reg .u64 t; cvta.to.shared.u64 t, %1; cvt.u32.u64 %0, t; }"
        : "=r"(a) : "l"(p));
    return a;
}

__device__ __forceinline__ void ldsm_x4(uint32_t (&r)[4], uint32_t addr) {
    asm volatile("ldmatrix.sync.aligned.m8n8.x4.shared.b16 {%0,%1,%2,%3}, [%4];"
        : "=r"(r[0]), "=r"(r[1]), "=r"(r[2]), "=r"(r[3]) : "r"(addr));
}
__device__ __forceinline__ void ldsm_x4t(uint32_t (&r)[4], uint32_t addr) {
    asm volatile("ldmatrix.sync.aligned.m8n8.x4.trans.shared.b16 {%0,%1,%2,%3}, [%4];"
        : "=r"(r[0]), "=r"(r[1]), "=r"(r[2]), "=r"(r[3]) : "r"(addr));
}
__device__ __forceinline__ void mma16816(float (&c)[4], const uint32_t (&a)[4],
                                         uint32_t b0, uint32_t b1) {
    asm volatile(
        "mma.sync.aligned.m16n8k16.row.col.f32.f16.f16.f32 "
        "{%0,%1,%2,%3}, {%4,%5,%6,%7}, {%8,%9}, {%0,%1,%2,%3};"
        : "+f"(c[0]), "+f"(c[1]), "+f"(c[2]), "+f"(c[3])
        : "r"(a[0]), "r"(a[1]), "r"(a[2]), "r"(a[3]), "r"(b0), "r"(b1));
}

#define CP16(dst, src) \
    asm volatile("cp.async.cg.shared.global [%0], [%1], 16;" :: "r"(dst), "l"(src))
#define CP_COMMIT() asm volatile("cp.async.commit_group;" ::: "memory")

__device__ __forceinline__ uint32_t pack2h(float v0, float v1) {
    __half2 h = __floats2half2_rn(v0, v1);   // v0 -> low, v1 -> high
    return *(uint32_t*)&h;
}

// ---------------------------------------------------------------------------
// fp32 -> fp16 convert for x
// ---------------------------------------------------------------------------
__global__ __launch_bounds__(256) void conv_x_kernel(const float* __restrict__ in, int n4)
{
    int i = blockIdx.x * blockDim.x + threadIdx.x;
    if (i >= n4) return;
    float4 v = ((const float4*)in)[i];
    ((uint32_t*)g_x16)[i * 2 + 0] = pack2h(v.x, v.y);
    ((uint32_t*)g_x16)[i * 2 + 1] = pack2h(v.z, v.w);
}

// ---------------------------------------------------------------------------
// Transpose + convert: W [K=1024, N] -> Wt fp16 [N, K]
// ---------------------------------------------------------------------------
template <int TGT>
__global__ __launch_bounds__(256) void tconv_kernel(const float* __restrict__ W, int Ncols)
{
    __shared__ float t[32][33];
    int n0 = blockIdx.x * 32, k0 = blockIdx.y * 32;
    int tx = threadIdx.x, ty = threadIdx.y;   // (32,8)
#pragma unroll
    for (int i = 0; i < 32; i += 8)
        t[ty + i][tx] = W[(size_t)(k0 + ty + i) * Ncols + n0 + tx];
    __syncthreads();
    __half* Dst = (TGT == 0) ? g_wa16 : g_wp16;
#pragma unroll
    for (int i = 0; i < 32; i += 8) {
        float v = t[tx][ty + i];
        Dst[(size_t)(n0 + ty + i) * 1024 + k0 + tx] = __float2half_rn(v);
    }
}

// ---------------------------------------------------------------------------
// mma.sync fp16 GEMM: C[M=8192, NTOT] = A[M,1024] @ Wt[NTOT,1024]^T + bias
// Block 128x128, 8 warps (32x64 warp tile), K-chunk 64, double buffered.
// MODE 0: scatter q/k/v fp16. MODE 1: fp32 out.
// ---------------------------------------------------------------------------
constexpr int GSTRIDE = 144;                // bytes per smem row (72 halves: 64+8 pad)
constexpr int GTILE = 128 * GSTRIDE;        // 18432 B per array
constexpr int GSTAGE = 2 * GTILE;           // A + B = 36864
constexpr int GEMM_SMEM = 2 * GSTAGE;       // 73728

template <int NTOT, int MODE>
__global__ __launch_bounds__(256, 2) void mgemm_kernel(const float* __restrict__ bias,
                                                       float* __restrict__ Out)
{
    extern __shared__ __align__(128) uint8_t smraw[];
    const uint32_t sb = smem_u32(smraw);
    const int tid = threadIdx.x;
    const int wid = tid >> 5, lane = tid & 31;
    const int wM = wid & 3, wN = wid >> 2;
    const int lr = lane & 7, lm = lane >> 3;
    const int gq = lane >> 2, cq = lane & 3;
    const int bm = blockIdx.y * 128;
    const int bn = blockIdx.x * 128;

    const __half* __restrict__ A = (MODE == 0) ? g_x16 : g_y16;
    const __half* __restrict__ B = (MODE == 0) ? g_wa16 : g_wp16;

    float c[2][8][4];
#pragma unroll
    for (int a = 0; a < 2; a++)
#pragma unroll
        for (int b = 0; b < 8; b++)
#pragma unroll
            for (int d = 0; d < 4; d++) c[a][b][d] = 0.0f;

    auto fill = [&](int st, int kc) {
        uint32_t base = sb + st * GSTAGE;
#pragma unroll
        for (int i = tid; i < 1024; i += 256) {
            int row = i >> 3, seg = i & 7;
            uint32_t off = (uint32_t)(row * GSTRIDE + seg * 16);
            size_t ga = (size_t)(bm + row) * 1024 + kc * 64 + seg * 8;
            size_t gb = (size_t)(bn + row) * 1024 + kc * 64 + seg * 8;
            CP16(base + off,         A + ga);
            CP16(base + GTILE + off, B + gb);
        }
        CP_COMMIT();
    };

    fill(0, 0);
    fill(1, 1);

    for (int kc = 0; kc < 16; kc++) {
        const int st = kc & 1;
        if (kc == 15) asm volatile("cp.async.wait_group 0;" ::: "memory");
        else          asm volatile("cp.async.wait_group 1;" ::: "memory");
        __syncthreads();

        const uint32_t base = sb + st * GSTAGE;
#pragma unroll
        for (int ks = 0; ks < 4; ks++) {
            uint32_t ah[2][4];
#pragma unroll
            for (int mf = 0; mf < 2; mf++) {
                int row = wM * 32 + mf * 16 + (lm & 1) * 8 + lr;
                int col = ks * 16 + (lm >> 1) * 8;
                ldsm_x4(ah[mf], base + row * GSTRIDE + col * 2);
            }
#pragma unroll
            for (int jj = 0; jj < 4; jj++) {
                int rowB = wN * 64 + jj * 16 + (lm >> 1) * 8 + lr;
                int colB = ks * 16 + (lm & 1) * 8;
                uint32_t bh_[4];
                ldsm_x4(bh_, base + GTILE + rowB * GSTRIDE + colB * 2);
#pragma unroll
                for (int mf = 0; mf < 2; mf++)
#pragma unroll
                    for (int nn = 0; nn < 2; nn++)
                        mma16816(c[mf][jj * 2 + nn], ah[mf], bh_[nn * 2], bh_[nn * 2 + 1]);
            }
        }
        __syncthreads();
        if (kc + 2 < 16) fill(st, kc + 2);
    }

    // Epilogue
#pragma unroll
    for (int mf = 0; mf < 2; mf++) {
        int row0 = bm + wM * 32 + mf * 16 + gq;
#pragma unroll
        for (int j = 0; j < 8; j++) {
            int n = bn + wN * 64 + j * 8 + 2 * cq;
            if (MODE == 0) {
                float b0 = bias[n], b1 = bias[n + 1];
                const int which = n >> 10;
                const int dd = n & 1023;
                const int h = dd >> 6, hd = dd & 63;
                __half* pq = (which == 0) ? g_q16 : (which == 1) ? g_k16 : g_v16;
                const float sc = (which == 0) ? 0.125f : 1.0f;
#pragma unroll
                for (int half_ = 0; half_ < 2; half_++) {
                    int m = row0 + half_ * 8;
                    int b_ = m >> 11, s_ = m & 2047;
                    float v0 = (c[mf][j][half_ * 2 + 0] + b0) * sc;
                    float v1 = (c[mf][j][half_ * 2 + 1] + b1) * sc;
                    size_t idx = (((size_t)(b_ * Hh + h)) * Ss + s_) * HD + hd;
                    *(uint32_t*)&pq[idx] = pack2h(v0, v1);
                }
            } else {
                float b0 = bias[n], b1 = bias[n + 1];
#pragma unroll
                for (int half_ = 0; half_ < 2; half_++) {
                    int m = row0 + half_ * 8;
                    float2 o;
                    o.x = c[mf][j][half_ * 2 + 0] + b0;
                    o.y = c[mf][j][half_ * 2 + 1] + b1;
                    *(float2*)&Out[(size_t)m * NTOT + n] = o;
                }
            }
        }
    }
}

// ---------------------------------------------------------------------------
// Flash attention fp16: 256 thr = 8 warps, Q tile 128 rows, K/V tile 64.
// cp.async double-buffered K/V stages + dedicated Q smem region.
// ---------------------------------------------------------------------------
constexpr int ATB = 64 * 144;                 // 9216 B per K/V array
constexpr int ATT_STAGE = 2 * ATB;            // K + V = 18432
constexpr int ATT_QOFF = 2 * ATT_STAGE;       // 36864
constexpr int ATT_QSZ = 128 * 144;            // 18432
constexpr int ATT_SMEM = ATT_QOFF + ATT_QSZ;  // 55296

__global__ __launch_bounds__(256, 2) void attn_kernel()
{
    extern __shared__ __align__(128) uint8_t smd[];
    const uint32_t sb = smem_u32(smd);
    const int qt = blockIdx.x, bh = blockIdx.y;
    const int tid = threadIdx.x;
    const int w = tid >> 5, lane = tid & 31;
    const int lr = lane & 7, lm = lane >> 3;
    const int gq = lane >> 2, cq = lane & 3;

    const size_t bhoff = (size_t)bh * Ss * HD;
    const uint32_t qb = sb + ATT_QOFF;

    // stage Q tile (128 rows x 64 halves = 128B/row)
    {
        const uint4* q4 = (const uint4*)(g_q16 + bhoff + (size_t)qt * 128 * HD);
#pragma unroll
        for (int i = tid; i < 1024; i += 256) {
            int row = i >> 3, seg = i & 7;
            *(uint4*)(smd + ATT_QOFF + row * 144 + seg * 16) = q4[row * 8 + seg];
        }
    }

    const int NT = 2 * qt + 2;    // number of 64-key tiles

    auto fill = [&](int st, int kt) {
        uint32_t base = sb + st * ATT_STAGE;
        const size_t ko = bhoff + (size_t)kt * 64 * HD;
#pragma unroll
        for (int t = 0; t < 2; t++) {
            int idx = tid + t * 256;          // 0..511
            int row = idx >> 3, seg = idx & 7;
            uint32_t o = (uint32_t)(row * 144 + seg * 16);
            size_t go = ko + (size_t)row * HD + seg * 8;
            CP16(base + o,       g_k16 + go);
            CP16(base + ATB + o, g_v16 + go);
        }
        CP_COMMIT();
    };

    fill(0, 0);
    fill(1, 1);

    float m0 = -1e30f, m1 = -1e30f, l0 = 0.0f, l1 = 0.0f;
    float acc[8][4];
#pragma unroll
    for (int j = 0; j < 8; j++)
#pragma unroll
        for (int d = 0; d < 4; d++) acc[j][d] = 0.0f;

    for (int kt = 0; kt < NT; kt++) {
        const int st = kt & 1;
        if (kt + 1 < NT) asm volatile("cp.async.wait_group 1;" ::: "memory");
        else             asm volatile("cp.async.wait_group 0;" ::: "memory");
        __syncthreads();

        const uint32_t base = sb + st * ATT_STAGE;

        // S = Q @ K^T
        float s[8][4];
#pragma unroll
        for (int j = 0; j < 8; j++)
#pragma unroll
            for (int d = 0; d < 4; d++) s[j][d] = 0.0f;

#pragma unroll
        for (int ks = 0; ks < 4; ks++) {
            uint32_t qh_[4];
            {
                int rowQ = w * 16 + (lm & 1) * 8 + lr;
                int colQ = ks * 16 + (lm >> 1) * 8;
                ldsm_x4(qh_, qb + rowQ * 144 + colQ * 2);
            }
#pragma unroll
            for (int jj = 0; jj < 2; jj++) {
                uint32_t bh0[4], bh1[4];
                {
                    int rowB = jj * 32 + (lm >> 1) * 8 + lr;
                    int colB = ks * 16 + (lm & 1) * 8;
                    uint32_t adB = base + rowB * 144 + colB * 2;
                    ldsm_x4(bh0, adB);
                    ldsm_x4(bh1, adB + 16 * 144);
                }
                int j0 = jj * 4;
                mma16816(s[j0 + 0], qh_, bh0[0], bh0[1]);
                mma16816(s[j0 + 1], qh_, bh0[2], bh0[3]);
                mma16816(s[j0 + 2], qh_, bh1[0], bh1[1]);
                mma16816(s[j0 + 3], qh_, bh1[2], bh1[3]);
            }
        }

        // causal mask (tiles crossing this warp's rows)
        if (kt * 64 + 63 > qt * 128 + w * 16) {
            int rg0 = qt * 128 + w * 16 + gq, rg1 = rg0 + 8;
#pragma unroll
            for (int j = 0; j < 8; j++) {
                int ck = kt * 64 + j * 8 + 2 * cq;
                if (ck > rg0)     s[j][0] = -1e30f;
                if (ck + 1 > rg0) s[j][1] = -1e30f;
                if (ck > rg1)     s[j][2] = -1e30f;
                if (ck + 1 > rg1) s[j][3] = -1e30f;
            }
        }

        // online softmax
        float tm0 = -1e30f, tm1 = -1e30f;
#pragma unroll
        for (int j = 0; j < 8; j++) {
            tm0 = fmaxf(tm0, fmaxf(s[j][0], s[j][1]));
            tm1 = fmaxf(tm1, fmaxf(s[j][2], s[j][3]));
        }
        tm0 = fmaxf(tm0, __shfl_xor_sync(0xffffffffu, tm0, 1));
        tm0 = fmaxf(tm0, __shfl_xor_sync(0xffffffffu, tm0, 2));
        tm1 = fmaxf(tm1, __shfl_xor_sync(0xffffffffu, tm1, 1));
        tm1 = fmaxf(tm1, __shfl_xor_sync(0xffffffffu, tm1, 2));
        float mn0 = fmaxf(m0, tm0), mn1 = fmaxf(m1, tm1);
        float a0 = __expf(m0 - mn0), a1 = __expf(m1 - mn1);
        float rs0 = 0.0f, rs1 = 0.0f;
#pragma unroll
        for (int j = 0; j < 8; j++) {
            s[j][0] = __expf(s[j][0] - mn0);
            s[j][1] = __expf(s[j][1] - mn0);
            s[j][2] = __expf(s[j][2] - mn1);
            s[j][3] = __expf(s[j][3] - mn1);
            rs0 += s[j][0] + s[j][1];
            rs1 += s[j][2] + s[j][3];
        }
        rs0 += __shfl_xor_sync(0xffffffffu, rs0, 1);
        rs0 += __shfl_xor_sync(0xffffffffu, rs0, 2);
        rs1 += __shfl_xor_sync(0xffffffffu, rs1, 1);
        rs1 += __shfl_xor_sync(0xffffffffu, rs1, 2);
        l0 = l0 * a0 + rs0;
        l1 = l1 * a1 + rs1;
        m0 = mn0;
        m1 = mn1;
#pragma unroll
        for (int j = 0; j < 8; j++) {
            acc[j][0] *= a0; acc[j][1] *= a0;
            acc[j][2] *= a1; acc[j][3] *= a1;
        }

        // O += P @ V (P packed fp16 in registers)
#pragma unroll
        for (int ks = 0; ks < 4; ks++) {
            uint32_t pa[4];
            pa[0] = pack2h(s[2 * ks][0],     s[2 * ks][1]);
            pa[1] = pack2h(s[2 * ks][2],     s[2 * ks][3]);
            pa[2] = pack2h(s[2 * ks + 1][0], s[2 * ks + 1][1]);
            pa[3] = pack2h(s[2 * ks + 1][2], s[2 * ks + 1][3]);
#pragma unroll
            for (int jj = 0; jj < 2; jj++) {
                uint32_t vh0[4], vh1[4];
                {
                    int rowV = ks * 16 + (lm & 1) * 8 + lr;
                    int colV = jj * 32 + (lm >> 1) * 8;
                    uint32_t adV = base + ATB + rowV * 144 + colV * 2;
                    ldsm_x4t(vh0, adV);
                    ldsm_x4t(vh1, adV + 32);
                }
                int j0 = jj * 4;
                mma16816(acc[j0 + 0], pa, vh0[0], vh0[1]);
                mma16816(acc[j0 + 1], pa, vh0[2], vh0[3]);
                mma16816(acc[j0 + 2], pa, vh1[0], vh1[1]);
                mma16816(acc[j0 + 3], pa, vh1[2], vh1[3]);
            }
        }
        __syncthreads();
        if (kt + 2 < NT) fill(st, kt + 2);
    }

    // epilogue: normalize, convert, store y fp16
    float i0 = 1.0f / l0, i1 = 1.0f / l1;
    const int b_ = bh >> 4, h = bh & 15;
    const int sr0 = qt * 128 + w * 16 + gq, sr1 = sr0 + 8;
#pragma unroll
    for (int j = 0; j < 8; j++) {
        int hd = j * 8 + 2 * cq;
        size_t o0 = ((size_t)b_ * Ss + sr0) * Dd + h * HD + hd;
        *(uint32_t*)&g_y16[o0] = pack2h(acc[j][0] * i0, acc[j][1] * i0);
        size_t o1 = ((size_t)b_ * Ss + sr1) * Dd + h * HD + hd;
        *(uint32_t*)&g_y16[o1] = pack2h(acc[j][2] * i1, acc[j][3] * i1);
    }
}

// ---------------------------------------------------------------------------
extern "C" void kernel_launch(void* const* d_in, const int* in_sizes, int n_in,
                              void* d_out, int out_size)
{
    const float* x      = (const float*)d_in[0];
    const float* W_attn = (const float*)d_in[1];
    const float* b_attn = (const float*)d_in[2];
    const float* W_proj = (const float*)d_in[3];
    const float* b_proj = (const float*)d_in[4];
    float* out = (float*)d_out;

    cudaFuncSetAttribute(mgemm_kernel<3072, 0>,
                         cudaFuncAttributeMaxDynamicSharedMemorySize, GEMM_SMEM);
    cudaFuncSetAttribute(mgemm_kernel<1024, 1>,
                         cudaFuncAttributeMaxDynamicSharedMemorySize, GEMM_SMEM);
    cudaFuncSetAttribute(attn_kernel,
                         cudaFuncAttributeMaxDynamicSharedMemorySize, ATT_SMEM);

    // 0) fp16 conversions
    int n4 = Mrows * Dd / 4;
    conv_x_kernel<<<(n4 + 255) / 256, 256>>>(x, n4);
    tconv_kernel<0><<<dim3(3072 / 32, 1024 / 32), dim3(32, 8)>>>(W_attn, 3072);
    tconv_kernel<1><<<dim3(1024 / 32, 1024 / 32), dim3(32, 8)>>>(W_proj, 1024);

    // 1) QKV GEMM -> q/k/v fp16
    mgemm_kernel<3072, 0><<<dim3(3072 / 128, Mrows / 128), 256, GEMM_SMEM>>>(
        b_attn, nullptr);

    // 2) causal flash attention -> y fp16 (128-row q tiles)
    attn_kernel<<<dim3(Ss / 128, Bb * Hh), 256, ATT_SMEM>>>();

    // 3) output projection -> out fp32
    mgemm_kernel<1024, 1><<<dim3(1024 / 128, Mrows / 128), 256, GEMM_SMEM>>>(
        b_proj, out);
}